// round 11
// baseline (speedup 1.0000x reference)
#include <cuda_runtime.h>
#include <cuda_bf16.h>

// ---------------------------------------------------------------------------
// PrecondWL: out[node] = sum over node's pins of clamp(w[net],1)/(deg[net]-1)
// (deg>1 only), movable nodes only.
//
// Phase 0: out[i]=0 for fixed nodes (no deps).
// Phase 1: cnet[n] = deg>1 ? max(w,1)/(deg-1) : 0   (streaming, vec4)
//          + verify node CSR is uniform degree-4 (starts[i]==4i), publish a
//            replay-safe flag through the grid barrier.
// Phase 2 (uniform): out[i] = cnet[p2n[n2p4[i].x]] + ... (pure gather loop,
//          no starts loads, no branches). 16M random 4B gathers ->
//          L1tex wavefront floor (~103K cyc/SM); we run ~88% of it.
// Phase 2 (fallback): generic CSR walk (correct for arbitrary inputs).
// Single persistent kernel, sense-reversing grid barrier between phases.
// ---------------------------------------------------------------------------

#define N_NETS_MAX 2000000
__device__ float    g_cnet[N_NETS_MAX + 4];
__device__ unsigned g_bar_count = 0;
__device__ unsigned g_bar_sense = 0;
__device__ unsigned g_ok_count  = 0;   // #blocks that saw uniform degree-4
__device__ unsigned g_uniform   = 0;   // verdict for THIS replay (set by releaser)

__device__ __forceinline__ float node_generic(const int* __restrict__ n2p,
                                              const int* __restrict__ pin2net,
                                              int s, int e) {
    float r = 0.0f;
    for (int j = s; j < e; ++j) {
        int p = __ldcs(n2p + j);
        int n = __ldcg(pin2net + p);
        r += __ldg(g_cnet + n);
    }
    return r;
}

__global__ void __launch_bounds__(256)
precond_fused_kernel(const float* __restrict__ net_weights,
                     const int*   __restrict__ net2pin,      // starts, n_nets+1
                     const int*   __restrict__ n2p_start,    // starts, num_nodes+1
                     const int*   __restrict__ n2p,          // node->pin flat (perm)
                     const int*   __restrict__ pin2net,
                     const int*   __restrict__ movable_ptr,  // may be null
                     int movable_const,
                     float* __restrict__ out,
                     int n_nets, int num_nodes, int nblocks)
{
    const int tid      = blockIdx.x * blockDim.x + threadIdx.x;
    const int nthreads = nblocks * blockDim.x;
    const int movable  = movable_ptr ? __ldg(movable_ptr) : movable_const;

    // ---------------- Phase 0: fixed-node zeros ----------------------------
    for (int i = movable + tid; i < num_nodes; i += nthreads)
        __stcs(out + i, 0.0f);

    // ---------------- Phase 1a: verify uniform degree-4 node CSR ----------
    int ok = 1;
    for (int i = tid; i <= num_nodes; i += nthreads)
        ok &= (__ldcs(n2p_start + i) == 4 * i);

    // ---------------- Phase 1b: per-net contribution (vectorized x4) ------
    const int nq = n_nets >> 2;
    for (int q = tid; q < nq; q += nthreads) {
        int4   s4  = __ldcs(reinterpret_cast<const int4*>(net2pin) + q);
        int    s4e = __ldcs(net2pin + 4 * q + 4);
        float4 w4  = __ldcs(reinterpret_cast<const float4*>(net_weights) + q);
        int d0 = s4.y - s4.x;
        int d1 = s4.z - s4.y;
        int d2 = s4.w - s4.z;
        int d3 = s4e  - s4.w;
        float4 c;
        c.x = (d0 > 1) ? fmaxf(w4.x, 1.0f) / (float)(d0 - 1) : 0.0f;
        c.y = (d1 > 1) ? fmaxf(w4.y, 1.0f) / (float)(d1 - 1) : 0.0f;
        c.z = (d2 > 1) ? fmaxf(w4.z, 1.0f) / (float)(d2 - 1) : 0.0f;
        c.w = (d3 > 1) ? fmaxf(w4.w, 1.0f) / (float)(d3 - 1) : 0.0f;
        *(reinterpret_cast<float4*>(g_cnet) + q) = c;
    }
    for (int n = (nq << 2) + tid; n < n_nets; n += nthreads) {  // generic tail
        int s = __ldcs(net2pin + n);
        int e = __ldcs(net2pin + n + 1);
        int d = e - s;
        float w = fmaxf(__ldcs(net_weights + n), 1.0f);
        g_cnet[n] = (d > 1) ? (w / (float)(d - 1)) : 0.0f;
    }

    // ---------------- Grid barrier + uniformity verdict (replay-safe) -----
    int block_ok = __syncthreads_and(ok);
    if (threadIdx.x == 0) {
        if (block_ok) atomicAdd(&g_ok_count, 1u);
        __threadfence();  // publish cnet writes + ok_count before arriving
        unsigned oldsense = *((volatile unsigned*)&g_bar_sense);
        unsigned arrived  = atomicAdd(&g_bar_count, 1u);
        if (arrived == (unsigned)nblocks - 1u) {
            unsigned okc = *((volatile unsigned*)&g_ok_count);
            *((volatile unsigned*)&g_uniform) = (okc == (unsigned)nblocks);
            g_ok_count  = 0;                       // reset for next replay
            g_bar_count = 0;
            __threadfence();
            *((volatile unsigned*)&g_bar_sense) = oldsense ^ 1u;  // release
        } else {
            while (*((volatile unsigned*)&g_bar_sense) == oldsense) {
                __nanosleep(64);
            }
        }
        __threadfence();  // acquire
    }
    __syncthreads();
    const unsigned uniform = *((volatile unsigned*)&g_uniform);

    // ---------------- Phase 2: per-node gather-sum -------------------------
    if (uniform) {
        // Pure gather loop: pins at n2p[4i..4i+4), no starts, no branches.
        const int stride = nthreads;
        int i = tid;
        for (; i + stride < movable; i += 2 * stride) {
            int4 pa = __ldcs(reinterpret_cast<const int4*>(n2p) + i);
            int4 pb = __ldcs(reinterpret_cast<const int4*>(n2p) + (i + stride));
            int a0 = __ldcg(pin2net + pa.x);
            int a1 = __ldcg(pin2net + pa.y);
            int a2 = __ldcg(pin2net + pa.z);
            int a3 = __ldcg(pin2net + pa.w);
            int b0 = __ldcg(pin2net + pb.x);
            int b1 = __ldcg(pin2net + pb.y);
            int b2 = __ldcg(pin2net + pb.z);
            int b3 = __ldcg(pin2net + pb.w);
            float rA = (__ldg(g_cnet + a0) + __ldg(g_cnet + a1)) +
                       (__ldg(g_cnet + a2) + __ldg(g_cnet + a3));
            float rB = (__ldg(g_cnet + b0) + __ldg(g_cnet + b1)) +
                       (__ldg(g_cnet + b2) + __ldg(g_cnet + b3));
            __stcs(out + i, rA);
            __stcs(out + i + stride, rB);
        }
        if (i < movable) {
            int4 p = __ldcs(reinterpret_cast<const int4*>(n2p) + i);
            int a = __ldcg(pin2net + p.x);
            int b = __ldcg(pin2net + p.y);
            int c = __ldcg(pin2net + p.z);
            int d = __ldcg(pin2net + p.w);
            __stcs(out + i, (__ldg(g_cnet + a) + __ldg(g_cnet + b)) +
                            (__ldg(g_cnet + c) + __ldg(g_cnet + d)));
        }
    } else {
        // General CSR fallback (arbitrary degrees / starts).
        for (int i = tid; i < movable; i += nthreads) {
            int s = __ldcs(n2p_start + i);
            int e = __ldcs(n2p_start + i + 1);
            __stcs(out + i, node_generic(n2p, pin2net, s, e));
        }
    }
}

extern "C" void kernel_launch(void* const* d_in, const int* in_sizes, int n_in,
                              void* d_out, int out_size) {
    // metadata order:
    // 0: net_weights         f32 [N_NETS]
    // 1: flat_node2pin_start i32 [N_NODES+1]
    // 2: flat_node2pin       i32 [N_PINS]
    // 3: pin2net_map         i32 [N_PINS]
    // 4: flat_net2pin        i32 [N_NETS+1]
    // 5: num_movable_nodes   scalar buffer (if present)
    const float* net_weights = (const float*)d_in[0];
    const int*   n2p_start   = (const int*)d_in[1];
    const int*   n2p         = (const int*)d_in[2];
    const int*   pin2net     = (const int*)d_in[3];
    const int*   net2pin     = (const int*)d_in[4];
    const int*   movable_ptr = (n_in >= 6) ? (const int*)d_in[5] : nullptr;

    int n_nets    = in_sizes[4] - 1;
    int num_nodes = in_sizes[1] - 1;
    if (n_nets > N_NETS_MAX) n_nets = N_NETS_MAX;

    const int TPB = 256;

    // Exact-residency grid so the device barrier cannot deadlock.
    int dev = 0;
    cudaGetDevice(&dev);
    int sms = 148;
    cudaDeviceGetAttribute(&sms, cudaDevAttrMultiProcessorCount, dev);
    int bpm = 1;
    cudaOccupancyMaxActiveBlocksPerMultiprocessor(&bpm, precond_fused_kernel, TPB, 0);
    if (bpm < 1) bpm = 1;
    int grid = sms * bpm;

    precond_fused_kernel<<<grid, TPB>>>(
        net_weights, net2pin, n2p_start, n2p, pin2net,
        movable_ptr, 1800000, (float*)d_out,
        n_nets, num_nodes, grid);
}